// round 4
// baseline (speedup 1.0000x reference)
#include <cuda_runtime.h>
#include <math.h>

// Problem constants
#define NB   2
#define NK   4096
#define NP   16384
#define NKP  (NB*NK)          // 8192 keypoint rows
#define CBEV 256
#define HH   496
#define WW   432
#define R2   0.64f

// Grid for ball query (cell size = radius = 0.8)
#define GX 87
#define GY 100
#define GZ 5
#define NCELL (GX*GY*GZ)      // 43500
#define CAP 32

#define ROWS 16               // keypoint rows per block
#define PAIRS (ROWS/2)        // 8 row-pairs
#define GBLK (NKP/ROWS)       // 512 blocks
#define NPART (GBLK*2)        // BN partials: per (block, row-half)

// ---- scratch (static device globals; no allocation) ----
__device__ int   g_cellCnt[NB*NCELL];
__device__ int   g_cellPts[NB*NCELL*CAP];
__device__ float g_Z[NKP*128];
__device__ float g_psum[NPART*128];
__device__ float g_psq [NPART*128];
__device__ float g_scale[128];
__device__ float g_shift[128];

__device__ __forceinline__ int cellOf(float x, float lo) {
    return (int)floorf((x - lo) * 1.25f);
}

__global__ void k_init() {
    int i = blockIdx.x*blockDim.x + threadIdx.x;
    if (i < NB*NCELL) g_cellCnt[i] = 0;
}

__global__ void k_bin(const float* __restrict__ pts) {
    int i = blockIdx.x*blockDim.x + threadIdx.x;
    if (i >= NB*NP) return;
    int b = i / NP, p = i % NP;
    float x = pts[i*3+0], y = pts[i*3+1], z = pts[i*3+2];
    int cx = min(max(cellOf(x,   0.0f), 0), GX-1);
    int cy = min(max(cellOf(y, -39.68f),0), GY-1);
    int cz = min(max(cellOf(z,  -3.0f), 0), GZ-1);
    int cell = b*NCELL + (cx*GY + cy)*GZ + cz;
    int slot = atomicAdd(&g_cellCnt[cell], 1);
    if (slot < CAP) g_cellPts[cell*CAP + slot] = p;   // max-pool over set => order-invariant
}

// Mega-kernel: each block owns 16 keypoint rows end-to-end:
//   B) bilinear BEV gather (DRAM long pole) -> smem feature tile
//   A) ball query + MLP(4->32->64) + maxpool -> smem feature tile
//   C) 16x320 @ 320x128 GEMM (f32x2 FFMA) -> Z + deterministic BN partials
// GEMM/sa of some blocks hides under gather DRAM time of others.
__global__ void __launch_bounds__(256) k_main(
    const float* __restrict__ kps, const float* __restrict__ pts,
    const float* __restrict__ pf,  const float* __restrict__ bev,
    const float* __restrict__ W1, const float* __restrict__ b1,
    const float* __restrict__ W2, const float* __restrict__ b2,
    const float* __restrict__ Wf)
{
    __shared__ float fsp[PAIRS*640];     // pair p: element (k,parity) at [p*640 + 2k + parity]
    __shared__ float W1s[128], b1s[32], W2s[2048], b2s[64];
    __shared__ int   cidx[8][128];
    __shared__ float cd2 [8][128];
    __shared__ int4   offs[ROWS];        // per-row corner offsets (within a plane)
    __shared__ float4 wts [ROWS];        // per-row bilinear weights
    __shared__ int    rb  [ROWS];        // per-row batch index

    int t = threadIdx.x;
    int r0 = blockIdx.x * ROWS;

    // ---- stage weights + per-row interp params ----
    if (t < 128) W1s[t] = W1[t];
    for (int i = t; i < 2048; i += 256) W2s[i] = W2[i];
    if (t < 32) b1s[t] = b1[t];
    if (t >= 32 && t < 96) b2s[t-32] = b2[t-32];
    if (t >= 96 && t < 96+ROWS) {
        int r = t - 96, row = r0 + r;
        // match reference literally: (kx - 0)/0.16/1.0 ; (ky + 39.68)/0.16/1.0
        float x = kps[row*3+0] / 0.16f;
        float y = (kps[row*3+1] + 39.68f) / 0.16f;
        float fx = floorf(x), fy = floorf(y);
        int x0 = min(max((int)fx,     0), WW-1);
        int x1 = min(max((int)fx + 1, 0), WW-1);
        int y0 = min(max((int)fy,     0), HH-1);
        int y1 = min(max((int)fy + 1, 0), HH-1);
        offs[r] = make_int4(y0*WW + x0, y1*WW + x0, y0*WW + x1, y1*WW + x1);
        wts [r] = make_float4(((float)x1 - x)*((float)y1 - y),
                              ((float)x1 - x)*(y - (float)y0),
                              (x - (float)x0)*((float)y1 - y),
                              (x - (float)x0)*(y - (float)y0));
        rb  [r] = row >> 12;
    }
    __syncthreads();

    // ---- Phase B: BEV gather. thread t owns channel c=t for all 16 rows ----
    {
        int c = t;   // 0..255
        #pragma unroll 4
        for (int r = 0; r < ROWS; r++) {
            const float* p = bev + ((size_t)rb[r]*CBEV + c)*(size_t)(HH*WW);
            int4  o = offs[r];
            float4 w = wts[r];
            float Ia = __ldg(p + o.x), Ib = __ldg(p + o.y);
            float Ic = __ldg(p + o.z), Id = __ldg(p + o.w);
            fsp[(r>>1)*640 + 2*(64 + c) + (r&1)] = Ia*w.x + Ib*w.y + Ic*w.z + Id*w.w;
        }
    }

    // ---- Phase A: ball query + MLP. 8 warps, each handles 2 keypoints ----
    {
        int warp = t >> 5, lane = t & 31;
        for (int sub = 0; sub < 2; sub++) {
            int r = warp*2 + sub;
            int kpi = r0 + r;
            int b = kpi >> 12;
            float kx = kps[kpi*3+0], ky = kps[kpi*3+1], kz = kps[kpi*3+2];
            int cx = min(max(cellOf(kx,   0.0f), 0), GX-1);
            int cy = min(max(cellOf(ky, -39.68f),0), GY-1);
            int cz = min(max(cellOf(kz,  -3.0f), 0), GZ-1);
            const float* ptsb = pts + (size_t)b*NP*3;

            int n_l = 0;
            const int* cp_l = g_cellPts;
            if (lane < 27) {
                int ccx = cx + lane/9 - 1;
                int ccy = cy + (lane/3)%3 - 1;
                int ccz = cz + lane%3 - 1;
                if (ccx >= 0 && ccx < GX && ccy >= 0 && ccy < GY && ccz >= 0 && ccz < GZ) {
                    int cell = b*NCELL + (ccx*GY + ccy)*GZ + ccz;
                    n_l = min(g_cellCnt[cell], CAP);
                    cp_l = &g_cellPts[cell*CAP];
                }
            }
            int maxn = n_l;
            #pragma unroll
            for (int o = 16; o; o >>= 1) maxn = max(maxn, __shfl_xor_sync(0xffffffffu, maxn, o));

            int cnt = 0;
            for (int s = 0; s < maxn; s++) {
                bool act = s < n_l;
                int pi = act ? cp_l[s] : 0;
                float d2 = 1e30f;
                if (act) {
                    float ddx = ptsb[pi*3+0]-kx;
                    float ddy = ptsb[pi*3+1]-ky;
                    float ddz = ptsb[pi*3+2]-kz;
                    d2 = ddx*ddx + ddy*ddy + ddz*ddz;
                }
                bool val = act && (d2 < R2);
                unsigned m = __ballot_sync(0xffffffffu, val);
                int pos = cnt + __popc(m & ((1u<<lane)-1u));
                if (val && pos < 128) { cidx[warp][pos] = pi; cd2[warp][pos] = d2; }
                cnt += __popc(m);
            }
            if (cnt > 128) cnt = 128;
            __syncwarp();
            if (cnt > 32) {   // ultra-rare: keep 32 smallest d2 (same set as top_k)
                if (lane == 0) {
                    for (int i = 32; i < cnt; i++) {
                        float d = cd2[warp][i];
                        int mi = 0; float mv = cd2[warp][0];
                        for (int j = 1; j < 32; j++) { float v = cd2[warp][j]; if (v > mv) { mv = v; mi = j; } }
                        if (d < mv) { cd2[warp][mi] = d; cidx[warp][mi] = cidx[warp][i]; }
                    }
                }
                __syncwarp();
                cnt = 32;
            }

            float w10 = W1s[lane], w11 = W1s[32+lane], w12 = W1s[64+lane], w13 = W1s[96+lane];
            float b1v = b1s[lane];
            float a0 = 0.f, a1 = 0.f;   // relu >= 0 so 0-init == reference no-valid case
            const float* pfb = pf + (size_t)b*NP;
            for (int nIt = 0; nIt < cnt; nIt++) {
                int pi = cidx[warp][nIt];
                float dx = ptsb[pi*3+0]-kx;
                float dy = ptsb[pi*3+1]-ky;
                float dz = ptsb[pi*3+2]-kz;
                float f  = pfb[pi];
                float h = fmaxf(fmaf(dx,w10, fmaf(dy,w11, fmaf(dz,w12, fmaf(f,w13, b1v)))), 0.f);
                float t0 = b2s[lane], t1 = b2s[32+lane];
                #pragma unroll
                for (int j = 0; j < 32; j++) {
                    float hj = __shfl_sync(0xffffffffu, h, j);
                    t0 = fmaf(hj, W2s[j*64+lane],    t0);
                    t1 = fmaf(hj, W2s[j*64+32+lane], t1);
                }
                a0 = fmaxf(a0, fmaxf(t0, 0.f));
                a1 = fmaxf(a1, fmaxf(t1, 0.f));
            }
            fsp[(r>>1)*640 + 2*lane        + (r&1)] = a0;
            fsp[(r>>1)*640 + 2*(32 + lane) + (r&1)] = a1;
        }
    }
    __syncthreads();

    // ---- Phase C: GEMM. half h owns pairs h*4..h*4+3; thread col c=t&127 ----
    {
        int h = t >> 7, c = t & 127;
        unsigned long long acc[4];
        #pragma unroll
        for (int j = 0; j < 4; j++) acc[j] = 0ull;

        const float* wcol = Wf + c;
        const float* base = fsp + (h*4)*640;
        for (int k = 0; k < 320; k += 2) {
            float wa = wcol[(size_t)k*128];
            float wb = wcol[(size_t)(k+1)*128];
            unsigned long long w2a, w2b;
            asm("mov.b64 %0,{%1,%1};" : "=l"(w2a) : "f"(wa));
            asm("mov.b64 %0,{%1,%1};" : "=l"(w2b) : "f"(wb));
            #pragma unroll
            for (int j = 0; j < 4; j++) {
                longlong2 q = *(const longlong2*)(base + j*640 + 2*k);   // LDS.128 broadcast
                asm("fma.rn.f32x2 %0,%1,%2,%0;" : "+l"(acc[j]) : "l"((unsigned long long)q.x), "l"(w2a));
                asm("fma.rn.f32x2 %0,%1,%2,%0;" : "+l"(acc[j]) : "l"((unsigned long long)q.y), "l"(w2b));
            }
        }

        float s = 0.f, ss = 0.f;
        #pragma unroll
        for (int j = 0; j < 4; j++) {
            float zlo, zhi;
            asm("mov.b64 {%0,%1},%2;" : "=f"(zlo), "=f"(zhi) : "l"(acc[j]));
            int p = h*4 + j;
            g_Z[(size_t)(r0 + 2*p    )*128 + c] = zlo;
            g_Z[(size_t)(r0 + 2*p + 1)*128 + c] = zhi;
            s += zlo + zhi;
            ss += zlo*zlo + zhi*zhi;
        }
        g_psum[(blockIdx.x*2 + h)*128 + c] = s;
        g_psq [(blockIdx.x*2 + h)*128 + c] = ss;
    }
}

// Parallel BN stats: 1024 threads; 8 groups each reduce NPART/8 partials per channel.
__global__ void __launch_bounds__(1024) k_stats(
    const float* __restrict__ gamma, const float* __restrict__ beta)
{
    __shared__ float sh_s[1024], sh_q[1024];
    int t = threadIdx.x;
    int c = t & 127, g = t >> 7;
    float s = 0.f, ss = 0.f;
    for (int i = g; i < NPART; i += 8) { s += g_psum[i*128+c]; ss += g_psq[i*128+c]; }
    sh_s[t] = s; sh_q[t] = ss;
    __syncthreads();
    if (g == 0) {
        #pragma unroll
        for (int gg = 1; gg < 8; gg++) { s += sh_s[c + gg*128]; ss += sh_q[c + gg*128]; }
        float inv = 1.0f / (float)NKP;
        float mu  = s * inv;
        float var = ss * inv - mu*mu;
        float sc  = rsqrtf(var + 1e-5f) * gamma[c];
        g_scale[c] = sc;
        g_shift[c] = beta[c] - mu * sc;
    }
}

__global__ void k_norm(float* __restrict__ out) {
    int i = blockIdx.x*blockDim.x + threadIdx.x;
    int c = i & 127;
    out[i] = fmaxf(fmaf(g_Z[i], g_scale[c], g_shift[c]), 0.f);
}

extern "C" void kernel_launch(void* const* d_in, const int* /*in_sizes*/, int /*n_in*/,
                              void* d_out, int /*out_size*/) {
    const float* kps = (const float*)d_in[0];
    const float* pts = (const float*)d_in[1];
    const float* pf  = (const float*)d_in[2];
    const float* bev = (const float*)d_in[3];
    const float* W1  = (const float*)d_in[4];
    const float* b1  = (const float*)d_in[5];
    const float* W2  = (const float*)d_in[6];
    const float* b2  = (const float*)d_in[7];
    const float* Wf  = (const float*)d_in[8];
    const float* gm  = (const float*)d_in[9];
    const float* bt  = (const float*)d_in[10];

    k_init <<<(NB*NCELL + 255)/256, 256>>>();
    k_bin  <<<(NB*NP    + 255)/256, 256>>>(pts);
    k_main <<<GBLK, 256>>>(kps, pts, pf, bev, W1, b1, W2, b2, Wf);
    k_stats<<<1, 1024>>>(gm, bt);
    k_norm <<<(NKP*128)/256, 256>>>((float*)d_out);
}

// round 5
// speedup vs baseline: 1.1076x; 1.1076x over previous
#include <cuda_runtime.h>
#include <math.h>

// Problem constants
#define NB   2
#define NK   4096
#define NP   16384
#define NKP  (NB*NK)          // 8192 keypoint rows
#define CBEV 256
#define HH   496
#define WW   432
#define R2   0.64f

// Grid for ball query (cell size = radius = 0.8)
#define GX 87
#define GY 100
#define GZ 5
#define NCELL (GX*GY*GZ)      // 43500
#define CAP 32

// Fused sa+bev kernel: bev blocks first (DRAM long pole), sa blocks after.
#define BEV_BLKS (NKP/4)      // 2048 blocks, 4 rows each (16 LDGs in flight per thread)
#define SA_BLKS  (NKP/8)      // 1024 blocks, 8 warps = 8 keypoints each

// GEMM: 16 rows per block, 256 threads (two 8-row halves x 128 columns)
#define ROWS 16
#define PAIRS (ROWS/2)
#define GBLK (NKP/ROWS)       // 512 blocks
#define NPART (GBLK*2)        // 1024 BN partials

// ---- scratch (static device globals; no allocation) ----
__device__ int   g_cellCnt[NB*NCELL];
__device__ int   g_cellPts[NB*NCELL*CAP];
__device__ float g_sa[NKP*64];
__device__ float g_pbev[NKP*CBEV];
__device__ float g_Z[NKP*128];
__device__ float g_psum[NPART*128];
__device__ float g_psq [NPART*128];
__device__ float g_scale[128];
__device__ float g_shift[128];

__device__ __forceinline__ int cellOf(float x, float lo) {
    return (int)floorf((x - lo) * 1.25f);
}

__global__ void k_init() {
    int i = blockIdx.x*blockDim.x + threadIdx.x;
    if (i < NB*NCELL) g_cellCnt[i] = 0;
}

__global__ void k_bin(const float* __restrict__ pts) {
    int i = blockIdx.x*blockDim.x + threadIdx.x;
    if (i >= NB*NP) return;
    int b = i / NP, p = i % NP;
    float x = pts[i*3+0], y = pts[i*3+1], z = pts[i*3+2];
    int cx = min(max(cellOf(x,   0.0f), 0), GX-1);
    int cy = min(max(cellOf(y, -39.68f),0), GY-1);
    int cz = min(max(cellOf(z,  -3.0f), 0), GZ-1);
    int cell = b*NCELL + (cx*GY + cy)*GZ + cz;
    int slot = atomicAdd(&g_cellCnt[cell], 1);
    if (slot < CAP) g_cellPts[cell*CAP + slot] = p;   // max-pool over set => order-invariant
}

// Fused: blocks [0, BEV_BLKS) = bilinear BEV gather (DRAM-bound);
//        blocks [BEV_BLKS, ...) = ball query + MLP + maxpool (latency-bound, hides under DRAM).
__global__ void __launch_bounds__(256) k_sabev(
    const float* __restrict__ kps, const float* __restrict__ pts,
    const float* __restrict__ pf,  const float* __restrict__ bev,
    const float* __restrict__ W1, const float* __restrict__ b1,
    const float* __restrict__ W2, const float* __restrict__ b2)
{
    int t = threadIdx.x;

    if (blockIdx.x < BEV_BLKS) {
        // 4 rows per block; thread handles 2 rows x 2 channels = 16 independent LDGs.
        int c    = t & 127;
        int row0 = blockIdx.x*4 + (t >> 7)*2;
        #pragma unroll
        for (int rr = 0; rr < 2; rr++) {
            int row = row0 + rr;
            int b = row >> 12;
            // match reference literally: (kx - 0)/0.16/1.0 ; (ky + 39.68)/0.16/1.0
            float x = kps[row*3+0] / 0.16f;
            float y = (kps[row*3+1] + 39.68f) / 0.16f;
            float fx = floorf(x), fy = floorf(y);
            int x0 = min(max((int)fx,     0), WW-1);
            int x1 = min(max((int)fx + 1, 0), WW-1);
            int y0 = min(max((int)fy,     0), HH-1);
            int y1 = min(max((int)fy + 1, 0), HH-1);
            float wa = ((float)x1 - x)*((float)y1 - y);
            float wb = ((float)x1 - x)*(y - (float)y0);
            float wc = (x - (float)x0)*((float)y1 - y);
            float wd = (x - (float)x0)*(y - (float)y0);
            const float* p0 = bev + ((size_t)b*CBEV + c)*(size_t)(HH*WW);
            const float* p1 = p0 + (size_t)128*HH*WW;
            int oa = y0*WW + x0, ob = y1*WW + x0, oc = y0*WW + x1, od = y1*WW + x1;
            float A0 = __ldg(p0+oa), B0 = __ldg(p0+ob), C0 = __ldg(p0+oc), D0 = __ldg(p0+od);
            float A1 = __ldg(p1+oa), B1 = __ldg(p1+ob), C1 = __ldg(p1+oc), D1 = __ldg(p1+od);
            g_pbev[(size_t)row*CBEV + c]       = A0*wa + B0*wb + C0*wc + D0*wd;
            g_pbev[(size_t)row*CBEV + c + 128] = A1*wa + B1*wb + C1*wc + D1*wd;
        }
        return;
    }

    // ---- SA: one warp per keypoint, 8 warps per block ----
    __shared__ float W1s[128], b1s[32], W2s[2048], b2s[64];
    __shared__ int   cidx[8][128];
    __shared__ float cd2 [8][128];
    if (t < 128) W1s[t] = W1[t];
    for (int i = t; i < 2048; i += 256) W2s[i] = W2[i];
    if (t < 32) b1s[t] = b1[t];
    if (t < 64) b2s[t] = b2[t];
    __syncthreads();

    int warp = t >> 5, lane = t & 31;
    int kpi = (blockIdx.x - BEV_BLKS)*8 + warp;    // 0..8191
    int b = kpi >> 12;
    float kx = kps[kpi*3+0], ky = kps[kpi*3+1], kz = kps[kpi*3+2];
    int cx = min(max(cellOf(kx,   0.0f), 0), GX-1);
    int cy = min(max(cellOf(ky, -39.68f),0), GY-1);
    int cz = min(max(cellOf(kz,  -3.0f), 0), GZ-1);

    const float* ptsb = pts + (size_t)b*NP*3;

    // lane l < 27 owns neighbor cell l
    int n_l = 0;
    const int* cp_l = g_cellPts;
    if (lane < 27) {
        int ccx = cx + lane/9 - 1;
        int ccy = cy + (lane/3)%3 - 1;
        int ccz = cz + lane%3 - 1;
        if (ccx >= 0 && ccx < GX && ccy >= 0 && ccy < GY && ccz >= 0 && ccz < GZ) {
            int cell = b*NCELL + (ccx*GY + ccy)*GZ + ccz;
            n_l = min(g_cellCnt[cell], CAP);
            cp_l = &g_cellPts[cell*CAP];
        }
    }
    int maxn = n_l;
    #pragma unroll
    for (int o = 16; o; o >>= 1) maxn = max(maxn, __shfl_xor_sync(0xffffffffu, maxn, o));

    int cnt = 0;
    for (int s = 0; s < maxn; s++) {
        bool act = s < n_l;
        int pi = act ? cp_l[s] : 0;
        float d2 = 1e30f;
        if (act) {
            float ddx = ptsb[pi*3+0]-kx;
            float ddy = ptsb[pi*3+1]-ky;
            float ddz = ptsb[pi*3+2]-kz;
            d2 = ddx*ddx + ddy*ddy + ddz*ddz;
        }
        bool val = act && (d2 < R2);
        unsigned m = __ballot_sync(0xffffffffu, val);
        int pos = cnt + __popc(m & ((1u<<lane)-1u));
        if (val && pos < 128) { cidx[warp][pos] = pi; cd2[warp][pos] = d2; }
        cnt += __popc(m);
    }
    if (cnt > 128) cnt = 128;
    __syncwarp();
    if (cnt > 32) {   // ultra-rare: keep 32 smallest d2 (same set as top_k; order irrelevant for maxpool)
        if (lane == 0) {
            for (int i = 32; i < cnt; i++) {
                float d = cd2[warp][i];
                int mi = 0; float mv = cd2[warp][0];
                for (int j = 1; j < 32; j++) { float v = cd2[warp][j]; if (v > mv) { mv = v; mi = j; } }
                if (d < mv) { cd2[warp][mi] = d; cidx[warp][mi] = cidx[warp][i]; }
            }
        }
        __syncwarp();
        cnt = 32;
    }

    float w10 = W1s[lane], w11 = W1s[32+lane], w12 = W1s[64+lane], w13 = W1s[96+lane];
    float b1v = b1s[lane];
    float a0 = 0.f, a1 = 0.f;   // relu >= 0 so 0-init == reference no-valid case
    const float* pfb = pf + (size_t)b*NP;
    for (int nIt = 0; nIt < cnt; nIt++) {
        int pi = cidx[warp][nIt];
        float dx = ptsb[pi*3+0]-kx;
        float dy = ptsb[pi*3+1]-ky;
        float dz = ptsb[pi*3+2]-kz;
        float f  = pfb[pi];
        float h = fmaxf(fmaf(dx,w10, fmaf(dy,w11, fmaf(dz,w12, fmaf(f,w13, b1v)))), 0.f);
        float t0 = b2s[lane], t1 = b2s[32+lane];
        #pragma unroll
        for (int j = 0; j < 32; j++) {
            float hj = __shfl_sync(0xffffffffu, h, j);
            t0 = fmaf(hj, W2s[j*64+lane],    t0);
            t1 = fmaf(hj, W2s[j*64+32+lane], t1);
        }
        a0 = fmaxf(a0, fmaxf(t0, 0.f));
        a1 = fmaxf(a1, fmaxf(t1, 0.f));
    }
    g_sa[kpi*64 + lane]      = a0;
    g_sa[kpi*64 + 32 + lane] = a1;
}

// GEMM: 512 blocks x 256 threads. 16 rows/block; half h owns pairs h*4..h*4+3,
// thread col c = t&127. Row pairs packed as f32x2 (fma.rn.f32x2 == 2x scalar fma.rn).
__global__ void __launch_bounds__(256) k_gemm(const float* __restrict__ Wf)
{
    __shared__ float fsp[PAIRS*640];   // pair p: element (k,parity) at [p*640 + 2k + parity]
    int t = threadIdx.x;
    int r0 = blockIdx.x * ROWS;

    for (int i = t; i < ROWS*320; i += 256) {
        int r = i / 320, k = i - r*320;
        float v = (k < 64) ? g_sa[(size_t)(r0+r)*64 + k]
                           : g_pbev[(size_t)(r0+r)*CBEV + (k-64)];
        fsp[(r>>1)*640 + 2*k + (r&1)] = v;
    }
    __syncthreads();

    int h = t >> 7, c = t & 127;
    unsigned long long acc[4];
    #pragma unroll
    for (int j = 0; j < 4; j++) acc[j] = 0ull;

    const float* wcol = Wf + c;
    const float* base = fsp + (h*4)*640;
    for (int k = 0; k < 320; k += 2) {
        float wa = wcol[(size_t)k*128];
        float wb = wcol[(size_t)(k+1)*128];
        unsigned long long w2a, w2b;
        asm("mov.b64 %0,{%1,%1};" : "=l"(w2a) : "f"(wa));
        asm("mov.b64 %0,{%1,%1};" : "=l"(w2b) : "f"(wb));
        #pragma unroll
        for (int j = 0; j < 4; j++) {
            longlong2 q = *(const longlong2*)(base + j*640 + 2*k);   // LDS.128 broadcast
            asm("fma.rn.f32x2 %0,%1,%2,%0;" : "+l"(acc[j]) : "l"((unsigned long long)q.x), "l"(w2a));
            asm("fma.rn.f32x2 %0,%1,%2,%0;" : "+l"(acc[j]) : "l"((unsigned long long)q.y), "l"(w2b));
        }
    }

    float s = 0.f, ss = 0.f;
    #pragma unroll
    for (int j = 0; j < 4; j++) {
        float zlo, zhi;
        asm("mov.b64 {%0,%1},%2;" : "=f"(zlo), "=f"(zhi) : "l"(acc[j]));
        int p = h*4 + j;
        g_Z[(size_t)(r0 + 2*p    )*128 + c] = zlo;
        g_Z[(size_t)(r0 + 2*p + 1)*128 + c] = zhi;
        s += zlo + zhi;
        ss += zlo*zlo + zhi*zhi;
    }
    g_psum[(blockIdx.x*2 + h)*128 + c] = s;
    g_psq [(blockIdx.x*2 + h)*128 + c] = ss;
}

// BN stats: one block per channel; 256 threads tree-reduce 1024 partials. Deterministic.
__global__ void __launch_bounds__(256) k_stats(
    const float* __restrict__ gamma, const float* __restrict__ beta)
{
    __shared__ float sh_s[256], sh_q[256];
    int c = blockIdx.x, t = threadIdx.x;
    float s = 0.f, q = 0.f;
    #pragma unroll
    for (int i = t; i < NPART; i += 256) { s += g_psum[i*128+c]; q += g_psq[i*128+c]; }
    sh_s[t] = s; sh_q[t] = q;
    __syncthreads();
    #pragma unroll
    for (int o = 128; o; o >>= 1) {
        if (t < o) { sh_s[t] += sh_s[t+o]; sh_q[t] += sh_q[t+o]; }
        __syncthreads();
    }
    if (t == 0) {
        float inv = 1.0f / (float)NKP;
        float mu  = sh_s[0] * inv;
        float var = sh_q[0] * inv - mu*mu;
        float sc  = rsqrtf(var + 1e-5f) * gamma[c];
        g_scale[c] = sc;
        g_shift[c] = beta[c] - mu * sc;
    }
}

__global__ void k_norm(float* __restrict__ out) {
    int i = blockIdx.x*blockDim.x + threadIdx.x;
    int c = i & 127;
    out[i] = fmaxf(fmaf(g_Z[i], g_scale[c], g_shift[c]), 0.f);
}

extern "C" void kernel_launch(void* const* d_in, const int* /*in_sizes*/, int /*n_in*/,
                              void* d_out, int /*out_size*/) {
    const float* kps = (const float*)d_in[0];
    const float* pts = (const float*)d_in[1];
    const float* pf  = (const float*)d_in[2];
    const float* bev = (const float*)d_in[3];
    const float* W1  = (const float*)d_in[4];
    const float* b1  = (const float*)d_in[5];
    const float* W2  = (const float*)d_in[6];
    const float* b2  = (const float*)d_in[7];
    const float* Wf  = (const float*)d_in[8];
    const float* gm  = (const float*)d_in[9];
    const float* bt  = (const float*)d_in[10];

    k_init <<<(NB*NCELL + 255)/256, 256>>>();
    k_bin  <<<(NB*NP    + 255)/256, 256>>>(pts);
    k_sabev<<<BEV_BLKS + SA_BLKS, 256>>>(kps, pts, pf, bev, W1, b1, W2, b2);
    k_gemm <<<GBLK, 256>>>(Wf);
    k_stats<<<128, 256>>>(gm, bt);
    k_norm <<<(NKP*128)/256, 256>>>((float*)d_out);
}